// round 4
// baseline (speedup 1.0000x reference)
#include <cuda_runtime.h>
#include <math.h>

#define BB   32
#define NN   16384
#define DD   65
#define CH   64
#define KK   64
#define NBL  256
#define SCALE 0.1240347345892081f   /* 65^-0.5 */

// ---------------- scratch (device globals: no allocation allowed) ----------------
__device__ float g_partial[BB * 64 * DD];                 // per-(b,split) column sums
__device__ float g_q[BB * KK * DD];                       // queries (SCALE folded in)
__device__ float g_r[BB * DD];                            // gavg@Wr + br
__device__ float g_blk[(size_t)BB * KK * NBL * DD];       // block-attention output, 136 MB

__device__ __forceinline__ float gelu_exact(float v) {
    return 0.5f * v * (1.0f + erff(v * 0.70710678118654752f));
}

// ================= Kernel A: partial column sums of x over N =================
// grid (64 splits, B), 256 threads. Each block sums 256 rows of x[b] into g_partial.
__global__ void kA(const float* __restrict__ x) {
    int b = blockIdx.y, s = blockIdx.x;
    int warp = threadIdx.x >> 5, lane = threadIdx.x & 31;
    const float* xb = x + ((size_t)b * NN + (size_t)s * 256 + warp * 32) * DD;
    float a0 = 0.f, a1 = 0.f, a2 = 0.f;
    #pragma unroll 4
    for (int r = 0; r < 32; ++r) {
        const float* row = xb + r * DD;
        a0 += row[lane];
        a1 += row[lane + 32];
        if (lane == 0) a2 += row[64];
    }
    __shared__ float sm[8][DD];
    sm[warp][lane] = a0;
    sm[warp][lane + 32] = a1;
    if (lane == 0) sm[warp][64] = a2;
    __syncthreads();
    if (threadIdx.x < DD) {
        float t = 0.f;
        #pragma unroll
        for (int w = 0; w < 8; ++w) t += sm[w][threadIdx.x];
        g_partial[(b * 64 + s) * DD + threadIdx.x] = t;
    }
}

// ================= Kernel B: gavg -> q (scaled), r = gavg@Wr+br =================
// grid (B, 16 slices of the 4160 q outputs), 256 threads.
__global__ void kB(const float* __restrict__ Wq1, const float* __restrict__ bq1,
                   const float* __restrict__ Wq2, const float* __restrict__ bq2,
                   const float* __restrict__ Wr,  const float* __restrict__ br) {
    int b = blockIdx.x, slice = blockIdx.y;
    __shared__ float gavg[DD], h[DD];
    int t = threadIdx.x;
    if (t < DD) {
        float s = 0.f;
        for (int p = 0; p < 64; ++p) s += g_partial[(b * 64 + p) * DD + t];
        gavg[t] = s * (1.0f / (float)NN);
    }
    __syncthreads();
    if (t < DD) {
        float acc = bq1[t];
        for (int e = 0; e < DD; ++e) acc = fmaf(gavg[e], Wq1[e * DD + t], acc);
        h[t] = gelu_exact(acc);
        if (slice == 0) {
            float r = br[t];
            for (int e = 0; e < DD; ++e) r = fmaf(gavg[e], Wr[e * DD + t], r);
            g_r[b * DD + t] = r;
        }
    }
    __syncthreads();
    int jend = (slice + 1) * 260;
    for (int j = slice * 260 + t; j < jend; j += 256) {
        float acc = bq2[j];
        for (int e = 0; e < DD; ++e) acc = fmaf(h[e], Wq2[e * (KK * DD) + j], acc);
        g_q[b * KK * DD + j] = acc * SCALE;
    }
}

// ================= Kernel C: fused per-chunk block attention =================
// grid (NBL, B), 256 threads (16x16 tile layout), dynamic smem 102688 B, 2 CTAs/SM.
// Smem layout (floats):
//   sxT   [65][64]  x transposed          (4160)
//   swq   [65][68]  Wk -> Wv -> qT        (4420)
//   sposT [65][64]  pos transposed        (4160)
//   skT   [65][64]  keys transposed       (4160)
//   sv    [64][68]  values                (4352)
//   ss    [64][68]  scores -> probs       (4352)
//   sb    [68]      bias                  (68)
#define KC_SMEM_FLOATS (4160 + 4420 + 4160 + 4160 + 4352 + 4352 + 68)

__global__ __launch_bounds__(256, 2) void kC(
    const float* __restrict__ x,
    const float* __restrict__ Wk, const float* __restrict__ bk,
    const float* __restrict__ Wv, const float* __restrict__ bv,
    const float* __restrict__ pos) {
    extern __shared__ float sm[];
    float* sxT   = sm;
    float* swq   = sm + 4160;
    float* sposT = swq + 4420;
    float* skT   = sposT + 4160;
    float* sv    = skT + 4160;
    float* ss    = sv + 4352;
    float* sb    = ss + 4352;

    int t = threadIdx.x;
    int tx = t & 15, ty = t >> 4;
    int warp = t >> 5, lane = t & 31;
    int chunk = blockIdx.x, b = blockIdx.y;

    // ---- load x (transposed), pos (transposed), Wk, bk ----
    const float* xc = x + ((size_t)b * NN + (size_t)chunk * CH) * DD;
    for (int i = t; i < CH * DD; i += 256) { int c = i / DD, e = i - c * DD; sxT[e * 64 + c] = xc[i]; }
    for (int i = t; i < CH * DD; i += 256) { int c = i / DD, e = i - c * DD; sposT[e * 64 + c] = pos[i]; }
    for (int i = t; i < DD * DD; i += 256) { int e = i / DD, d2 = i - e * DD; swq[e * 68 + d2] = Wk[i]; }
    if (t < DD) sb[t] = bk[t];
    __syncthreads();

    // ---- keys = gelu(x@Wk + bk) + pos, stored transposed skT[dd][c] ----
    {
        int c0 = ty * 4, d0 = tx * 4;
        float acc[4][4] = {};
        #pragma unroll 4
        for (int e = 0; e < DD; ++e) {
            float4 a = *(const float4*)(sxT + e * 64 + c0);
            float4 w = *(const float4*)(swq + e * 68 + d0);
            float av[4] = {a.x, a.y, a.z, a.w};
            float wv[4] = {w.x, w.y, w.z, w.w};
            #pragma unroll
            for (int i = 0; i < 4; ++i)
                #pragma unroll
                for (int j = 0; j < 4; ++j) acc[i][j] = fmaf(av[i], wv[j], acc[i][j]);
        }
        #pragma unroll
        for (int j = 0; j < 4; ++j) {
            float bj = sb[d0 + j];
            #pragma unroll
            for (int i = 0; i < 4; ++i) {
                float v = gelu_exact(acc[i][j] + bj) + sposT[(d0 + j) * 64 + (c0 + i)];
                skT[(d0 + j) * 64 + (c0 + i)] = v;
            }
        }
        if (t < CH) {  // dd = 64 tail, c = t
            float a2 = 0.f;
            for (int e = 0; e < DD; ++e) a2 = fmaf(sxT[e * 64 + t], swq[e * 68 + 64], a2);
            skT[64 * 64 + t] = gelu_exact(a2 + sb[64]) + sposT[64 * 64 + t];
        }
    }
    __syncthreads();

    // ---- swap weights: Wv, bv ----
    for (int i = t; i < DD * DD; i += 256) { int e = i / DD, d2 = i - e * DD; swq[e * 68 + d2] = Wv[i]; }
    if (t < DD) sb[t] = bv[t];
    __syncthreads();

    // ---- values = gelu(x@Wv + bv) + pos, stored sv[c][dd] ----
    {
        int c0 = ty * 4, d0 = tx * 4;
        float acc[4][4] = {};
        #pragma unroll 4
        for (int e = 0; e < DD; ++e) {
            float4 a = *(const float4*)(sxT + e * 64 + c0);
            float4 w = *(const float4*)(swq + e * 68 + d0);
            float av[4] = {a.x, a.y, a.z, a.w};
            float wv[4] = {w.x, w.y, w.z, w.w};
            #pragma unroll
            for (int i = 0; i < 4; ++i)
                #pragma unroll
                for (int j = 0; j < 4; ++j) acc[i][j] = fmaf(av[i], wv[j], acc[i][j]);
        }
        #pragma unroll
        for (int j = 0; j < 4; ++j) {
            float bj = sb[d0 + j];
            #pragma unroll
            for (int i = 0; i < 4; ++i)
                sv[(c0 + i) * 68 + (d0 + j)] =
                    gelu_exact(acc[i][j] + bj) + sposT[(d0 + j) * 64 + (c0 + i)];
        }
        if (t < CH) {  // dd = 64 tail, c = t
            float a2 = 0.f;
            for (int e = 0; e < DD; ++e) a2 = fmaf(sxT[e * 64 + t], swq[e * 68 + 64], a2);
            sv[t * 68 + 64] = gelu_exact(a2 + sb[64]) + sposT[64 * 64 + t];
        }
    }
    __syncthreads();

    // ---- load q transposed into swq: qT[dd][k] ----
    const float* qb = g_q + (size_t)b * KK * DD;
    for (int i = t; i < KK * DD; i += 256) { int k = i / DD, dd = i - k * DD; swq[dd * 68 + k] = qb[i]; }
    __syncthreads();

    // ---- scores[k][c] = SCALE * sum_dd qT[dd][k] * skT[dd][c] ----
    {
        int k0 = ty * 4, c0 = tx * 4;
        float acc[4][4] = {};
        #pragma unroll 4
        for (int dd = 0; dd < DD; ++dd) {
            float4 a = *(const float4*)(swq + dd * 68 + k0);
            float4 kk = *(const float4*)(skT + dd * 64 + c0);
            float av[4] = {a.x, a.y, a.z, a.w};
            float kv[4] = {kk.x, kk.y, kk.z, kk.w};
            #pragma unroll
            for (int i = 0; i < 4; ++i)
                #pragma unroll
                for (int j = 0; j < 4; ++j) acc[i][j] = fmaf(av[i], kv[j], acc[i][j]);
        }
        #pragma unroll
        for (int i = 0; i < 4; ++i)
            #pragma unroll
            for (int j = 0; j < 4; ++j) ss[(k0 + i) * 68 + (c0 + j)] = acc[i][j] * SCALE;
    }
    __syncthreads();

    // ---- softmax over c (in place, warp per row) ----
    for (int row = warp; row < KK; row += 8) {
        float v0 = ss[row * 68 + lane], v1 = ss[row * 68 + lane + 32];
        float m = fmaxf(v0, v1);
        #pragma unroll
        for (int o = 16; o > 0; o >>= 1) m = fmaxf(m, __shfl_xor_sync(0xffffffffu, m, o));
        float e0 = __expf(v0 - m), e1 = __expf(v1 - m);
        float s = e0 + e1;
        #pragma unroll
        for (int o = 16; o > 0; o >>= 1) s += __shfl_xor_sync(0xffffffffu, s, o);
        float inv = 1.0f / s;
        ss[row * 68 + lane] = e0 * inv;
        ss[row * 68 + lane + 32] = e1 * inv;
    }
    __syncthreads();

    // ---- blk[k][dd] = sum_c prob[k][c] * sv[c][dd] -> g_blk[b][k][chunk][dd] ----
    {
        int k0 = ty * 4, d0 = tx * 4;
        float acc[4][4] = {};
        #pragma unroll 4
        for (int c = 0; c < CH; ++c) {
            float av[4];
            #pragma unroll
            for (int i = 0; i < 4; ++i) av[i] = ss[(k0 + i) * 68 + c];
            float4 vv = *(const float4*)(sv + c * 68 + d0);
            float wv[4] = {vv.x, vv.y, vv.z, vv.w};
            #pragma unroll
            for (int i = 0; i < 4; ++i)
                #pragma unroll
                for (int j = 0; j < 4; ++j) acc[i][j] = fmaf(av[i], wv[j], acc[i][j]);
        }
        #pragma unroll
        for (int i = 0; i < 4; ++i) {
            size_t base = ((size_t)(b * KK + k0 + i) * NBL + chunk) * DD + d0;
            #pragma unroll
            for (int j = 0; j < 4; ++j) g_blk[base + j] = acc[i][j];
        }
        if (t < KK) {  // dd = 64 tail, k = t
            float a2 = 0.f;
            for (int c = 0; c < CH; ++c) a2 = fmaf(ss[t * 68 + c], sv[c * 68 + 64], a2);
            g_blk[((size_t)(b * KK + t) * NBL + chunk) * DD + 64] = a2;
        }
    }
}

// ================= Kernel D: cross-block attention + residual + LayerNorm =================
// grid (B*K), 256 threads. Smem: sblk 16640 | scs 256 | scq 68 | swr 8 | scomp 132 | sfin 2
#define KD_SMEM_FLOATS (16640 + 256 + 68 + 8 + 132 + 2)

__global__ __launch_bounds__(256, 2) void kD(
    const float* __restrict__ cq, const float* __restrict__ gamma,
    const float* __restrict__ beta, float* __restrict__ out) {
    extern __shared__ float sm[];
    float* sblk  = sm;
    float* scs   = sm + 16640;
    float* scq   = scs + 256;
    float* swr   = scq + 68;
    float* scomp = swr + 8;
    float* sfin  = scomp + 132;

    int t = threadIdx.x, warp = t >> 5, lane = t & 31;
    int bk = blockIdx.x;                 // = b*K + k
    int b = bk / KK;

    const float* src = g_blk + (size_t)bk * NBL * DD;
    for (int i = t; i < NBL * DD; i += 256) sblk[i] = src[i];
    if (t < DD) scq[t] = cq[t];
    __syncthreads();

    // cs[n] = SCALE * cross_q . blk[n,:]
    for (int n = warp; n < NBL; n += 8) {
        const float* row = sblk + n * DD;
        float p = row[lane] * scq[lane] + row[lane + 32] * scq[lane + 32];
        if (lane == 0) p += row[64] * scq[64];
        #pragma unroll
        for (int o = 16; o > 0; o >>= 1) p += __shfl_xor_sync(0xffffffffu, p, o);
        if (lane == 0) scs[n] = p * SCALE;
    }
    __syncthreads();

    // softmax over 256
    float v = scs[t];
    float m = v;
    #pragma unroll
    for (int o = 16; o > 0; o >>= 1) m = fmaxf(m, __shfl_xor_sync(0xffffffffu, m, o));
    if (lane == 0) swr[warp] = m;
    __syncthreads();
    if (t == 0) {
        float mm = swr[0];
        #pragma unroll
        for (int w = 1; w < 8; ++w) mm = fmaxf(mm, swr[w]);
        sfin[0] = mm;
    }
    __syncthreads();
    float e = __expf(v - sfin[0]);
    float s = e;
    #pragma unroll
    for (int o = 16; o > 0; o >>= 1) s += __shfl_xor_sync(0xffffffffu, s, o);
    if (lane == 0) swr[warp] = s;
    __syncthreads();
    if (t == 0) {
        float ts = 0.f;
        #pragma unroll
        for (int w = 0; w < 8; ++w) ts += swr[w];
        sfin[1] = ts;
    }
    __syncthreads();
    scs[t] = e / sfin[1];
    __syncthreads();

    // compressed[d] = sum_n cw[n] * blk[n][d]  (split n into two halves)
    if (t < 2 * DD) {
        int d = t % DD, g = t / DD;
        float a = 0.f;
        int n0 = g * 128;
        for (int n = n0; n < n0 + 128; ++n) a = fmaf(scs[n], sblk[n * DD + d], a);
        scomp[t] = a;
    }
    __syncthreads();
    if (t < DD) scomp[t] = scomp[t] + scomp[DD + t] + g_r[b * DD + t];
    __syncthreads();

    if (t == 0) {
        float mu = 0.f;
        for (int d = 0; d < DD; ++d) mu += scomp[d];
        mu *= (1.0f / DD);
        float var = 0.f;
        for (int d = 0; d < DD; ++d) { float dv = scomp[d] - mu; var += dv * dv; }
        var *= (1.0f / DD);
        sfin[0] = mu;
        sfin[1] = rsqrtf(var + 1e-5f);
    }
    __syncthreads();
    if (t < DD)
        out[(size_t)bk * DD + t] = (scomp[t] - sfin[0]) * sfin[1] * gamma[t] + beta[t];
}

// ================= launch =================
extern "C" void kernel_launch(void* const* d_in, const int* in_sizes, int n_in,
                              void* d_out, int out_size) {
    (void)in_sizes; (void)n_in; (void)out_size;
    const float* x    = (const float*)d_in[0];
    const float* Wq1  = (const float*)d_in[1];
    const float* bq1  = (const float*)d_in[2];
    const float* Wq2  = (const float*)d_in[3];
    const float* bq2  = (const float*)d_in[4];
    const float* Wk   = (const float*)d_in[5];
    const float* bk   = (const float*)d_in[6];
    const float* Wv   = (const float*)d_in[7];
    const float* bv   = (const float*)d_in[8];
    const float* cq   = (const float*)d_in[9];
    const float* pos  = (const float*)d_in[10];
    const float* Wr   = (const float*)d_in[11];
    const float* br   = (const float*)d_in[12];
    const float* gam  = (const float*)d_in[13];
    const float* bet  = (const float*)d_in[14];
    float* out = (float*)d_out;

    cudaFuncSetAttribute(kC, cudaFuncAttributeMaxDynamicSharedMemorySize,
                         KC_SMEM_FLOATS * (int)sizeof(float));
    cudaFuncSetAttribute(kD, cudaFuncAttributeMaxDynamicSharedMemorySize,
                         KD_SMEM_FLOATS * (int)sizeof(float));

    kA<<<dim3(64, BB), 256>>>(x);
    kB<<<dim3(BB, 16), 256>>>(Wq1, bq1, Wq2, bq2, Wr, br);
    kC<<<dim3(NBL, BB), 256, KC_SMEM_FLOATS * sizeof(float)>>>(x, Wk, bk, Wv, bv, pos);
    kD<<<BB * KK, 256, KD_SMEM_FLOATS * sizeof(float)>>>(cq, gam, bet, out);
}

// round 8
// speedup vs baseline: 1.1142x; 1.1142x over previous
#include <cuda_runtime.h>
#include <math.h>

#define BB   32
#define NN   16384
#define DD   65
#define CH   64
#define KK   64
#define NBL  256
#define SCALE 0.1240347345892081f   /* 65^-0.5 */

typedef unsigned long long u64;

// ---------------- scratch (device globals: no allocation allowed) ----------------
__device__ float g_partial[BB * 64 * DD];                 // per-(b,split) column sums
__device__ float g_q[BB * KK * DD];                       // queries (SCALE folded in)
__device__ float g_r[BB * DD];                            // gavg@Wr + br
__device__ float g_blk[(size_t)BB * KK * NBL * DD];       // block-attention output, 136 MB

__device__ __forceinline__ float gelu_exact(float v) {
    return 0.5f * v * (1.0f + erff(v * 0.70710678118654752f));
}

// ---- packed f32x2 helpers (FFMA2: double-rate fp32 on sm_103a, PTX-only) ----
__device__ __forceinline__ u64 pack2(float lo, float hi) {
    u64 r; asm("mov.b64 %0,{%1,%2};" : "=l"(r) : "f"(lo), "f"(hi)); return r;
}
__device__ __forceinline__ u64 dup2(float v) {
    u64 r; asm("mov.b64 %0,{%1,%1};" : "=l"(r) : "f"(v)); return r;
}
__device__ __forceinline__ u64 fma2(u64 a, u64 b, u64 c) {
    u64 d; asm("fma.rn.f32x2 %0,%1,%2,%3;" : "=l"(d) : "l"(a), "l"(b), "l"(c)); return d;
}
__device__ __forceinline__ float2 unpk(u64 v) {
    float2 f; asm("mov.b64 {%0,%1},%2;" : "=f"(f.x), "=f"(f.y) : "l"(v)); return f;
}

// ================= Kernel A: partial column sums of x over N =================
__global__ void kA(const float* __restrict__ x) {
    int b = blockIdx.y, s = blockIdx.x;
    int warp = threadIdx.x >> 5, lane = threadIdx.x & 31;
    const float* xb = x + ((size_t)b * NN + (size_t)s * 256 + warp * 32) * DD;
    float a0 = 0.f, a1 = 0.f, a2 = 0.f;
    #pragma unroll 4
    for (int r = 0; r < 32; ++r) {
        const float* row = xb + r * DD;
        a0 += row[lane];
        a1 += row[lane + 32];
        if (lane == 0) a2 += row[64];
    }
    __shared__ float sm[8][DD];
    sm[warp][lane] = a0;
    sm[warp][lane + 32] = a1;
    if (lane == 0) sm[warp][64] = a2;
    __syncthreads();
    if (threadIdx.x < DD) {
        float t = 0.f;
        #pragma unroll
        for (int w = 0; w < 8; ++w) t += sm[w][threadIdx.x];
        g_partial[(b * 64 + s) * DD + threadIdx.x] = t;
    }
}

// ================= Kernel B: gavg -> q (scaled), r = gavg@Wr+br =================
__global__ void kB(const float* __restrict__ Wq1, const float* __restrict__ bq1,
                   const float* __restrict__ Wq2, const float* __restrict__ bq2,
                   const float* __restrict__ Wr,  const float* __restrict__ br) {
    int b = blockIdx.x, slice = blockIdx.y;
    __shared__ float gavg[DD], h[DD];
    int t = threadIdx.x;
    if (t < DD) {
        float s = 0.f;
        for (int p = 0; p < 64; ++p) s += g_partial[(b * 64 + p) * DD + t];
        gavg[t] = s * (1.0f / (float)NN);
    }
    __syncthreads();
    if (t < DD) {
        float acc = bq1[t];
        for (int e = 0; e < DD; ++e) acc = fmaf(gavg[e], Wq1[e * DD + t], acc);
        h[t] = gelu_exact(acc);
        if (slice == 0) {
            float r = br[t];
            for (int e = 0; e < DD; ++e) r = fmaf(gavg[e], Wr[e * DD + t], r);
            g_r[b * DD + t] = r;
        }
    }
    __syncthreads();
    int jend = (slice + 1) * 260;
    for (int j = slice * 260 + t; j < jend; j += 256) {
        float acc = bq2[j];
        for (int e = 0; e < DD; ++e) acc = fmaf(h[e], Wq2[e * (KK * DD) + j], acc);
        g_q[b * KK * DD + j] = acc * SCALE;
    }
}

// ================= Kernel C: fused per-chunk block attention =================
// grid (NBL, B), 256 threads (16x16 tile layout), dynamic smem 102688 B, 2 CTAs/SM.
// Smem layout (floats):
//   sxT   [65][64]  x transposed          (4160)
//   swq   [65][68]  Wk -> Wv -> qT        (4420)
//   sposT [65][64]  pos transposed        (4160)
//   skT   [65][64]  keys transposed       (4160)
//   sv    [64][68]  values                (4352)
//   ss    [64][68]  scores -> probs       (4352)
//   sb    [68]      bias                  (68)
#define KC_SMEM_FLOATS (4160 + 4420 + 4160 + 4160 + 4352 + 4352 + 68)

__global__ __launch_bounds__(256, 2) void kC(
    const float* __restrict__ x,
    const float* __restrict__ Wk, const float* __restrict__ bk,
    const float* __restrict__ Wv, const float* __restrict__ bv,
    const float* __restrict__ pos) {
    extern __shared__ float sm[];
    float* sxT   = sm;
    float* swq   = sm + 4160;
    float* sposT = swq + 4420;
    float* skT   = sposT + 4160;
    float* sv    = skT + 4160;
    float* ss    = sv + 4352;
    float* sb    = ss + 4352;

    int t = threadIdx.x;
    int tx = t & 15, ty = t >> 4;
    int warp = t >> 5, lane = t & 31;
    int chunk = blockIdx.x, b = blockIdx.y;

    // ---- load x (transposed), pos (transposed), Wk, bk ----
    const float* xc = x + ((size_t)b * NN + (size_t)chunk * CH) * DD;
    for (int i = t; i < CH * DD; i += 256) { int c = i / DD, e = i - c * DD; sxT[e * 64 + c] = xc[i]; }
    for (int i = t; i < CH * DD; i += 256) { int c = i / DD, e = i - c * DD; sposT[e * 64 + c] = pos[i]; }
    for (int i = t; i < DD * DD; i += 256) { int e = i / DD, d2 = i - e * DD; swq[e * 68 + d2] = Wk[i]; }
    if (t < DD) sb[t] = bk[t];
    __syncthreads();

    // ---- keys = gelu(x@Wk + bk) + pos, stored transposed skT[dd][c] ----
    // Tile mapping: rows = dd (from Wk, ty), cols = c (from x, tx) -> all epilogue
    // accesses are lane-contiguous (no bank conflicts).
    {
        int d0 = ty * 4, c0 = tx * 4;
        u64 acc2[2][4] = {};
        #pragma unroll 4
        for (int e = 0; e < DD; ++e) {
            float4 a = *(const float4*)(swq + e * 68 + d0);   // Wk[e][d0..d0+3]
            float4 w = *(const float4*)(sxT + e * 64 + c0);   // x[c0..c0+3][e]
            u64 a01 = pack2(a.x, a.y), a23 = pack2(a.z, a.w);
            u64 w0 = dup2(w.x), w1 = dup2(w.y), w2 = dup2(w.z), w3 = dup2(w.w);
            acc2[0][0] = fma2(a01, w0, acc2[0][0]); acc2[0][1] = fma2(a01, w1, acc2[0][1]);
            acc2[0][2] = fma2(a01, w2, acc2[0][2]); acc2[0][3] = fma2(a01, w3, acc2[0][3]);
            acc2[1][0] = fma2(a23, w0, acc2[1][0]); acc2[1][1] = fma2(a23, w1, acc2[1][1]);
            acc2[1][2] = fma2(a23, w2, acc2[1][2]); acc2[1][3] = fma2(a23, w3, acc2[1][3]);
        }
        #pragma unroll
        for (int ip = 0; ip < 2; ++ip) {
            int i0 = d0 + ip * 2, i1 = i0 + 1;
            float b0 = sb[i0], b1 = sb[i1];
            #pragma unroll
            for (int j = 0; j < 4; ++j) {
                float2 p = unpk(acc2[ip][j]);
                skT[i0 * 64 + c0 + j] = gelu_exact(p.x + b0) + sposT[i0 * 64 + c0 + j];
                skT[i1 * 64 + c0 + j] = gelu_exact(p.y + b1) + sposT[i1 * 64 + c0 + j];
            }
        }
        if (t < CH) {  // dd = 64 tail, c = t
            float a2 = 0.f;
            for (int e = 0; e < DD; ++e) a2 = fmaf(sxT[e * 64 + t], swq[e * 68 + 64], a2);
            skT[64 * 64 + t] = gelu_exact(a2 + sb[64]) + sposT[64 * 64 + t];
        }
    }
    __syncthreads();

    // ---- swap weights: Wv, bv ----
    for (int i = t; i < DD * DD; i += 256) { int e = i / DD, d2 = i - e * DD; swq[e * 68 + d2] = Wv[i]; }
    if (t < DD) sb[t] = bv[t];
    __syncthreads();

    // ---- values = gelu(x@Wv + bv) + pos, stored sv[c][dd] ----
    // Tile mapping: rows = c (ty), cols = dd (tx) -> stores lane-contiguous;
    // pos add read from global (coalesced, L1/L2-resident 17 KB).
    {
        int c0 = ty * 4, d0 = tx * 4;
        u64 acc2[2][4] = {};
        #pragma unroll 4
        for (int e = 0; e < DD; ++e) {
            float4 a = *(const float4*)(sxT + e * 64 + c0);   // x[c0..][e]
            float4 w = *(const float4*)(swq + e * 68 + d0);   // Wv[e][d0..]
            u64 a01 = pack2(a.x, a.y), a23 = pack2(a.z, a.w);
            u64 w0 = dup2(w.x), w1 = dup2(w.y), w2 = dup2(w.z), w3 = dup2(w.w);
            acc2[0][0] = fma2(a01, w0, acc2[0][0]); acc2[0][1] = fma2(a01, w1, acc2[0][1]);
            acc2[0][2] = fma2(a01, w2, acc2[0][2]); acc2[0][3] = fma2(a01, w3, acc2[0][3]);
            acc2[1][0] = fma2(a23, w0, acc2[1][0]); acc2[1][1] = fma2(a23, w1, acc2[1][1]);
            acc2[1][2] = fma2(a23, w2, acc2[1][2]); acc2[1][3] = fma2(a23, w3, acc2[1][3]);
        }
        #pragma unroll
        for (int ip = 0; ip < 2; ++ip) {
            int c_0 = c0 + ip * 2, c_1 = c_0 + 1;
            #pragma unroll
            for (int j = 0; j < 4; ++j) {
                float2 p = unpk(acc2[ip][j]);
                float bj = sb[d0 + j];
                sv[c_0 * 68 + d0 + j] = gelu_exact(p.x + bj) + pos[c_0 * DD + d0 + j];
                sv[c_1 * 68 + d0 + j] = gelu_exact(p.y + bj) + pos[c_1 * DD + d0 + j];
            }
        }
        if (t < CH) {  // dd = 64 tail, c = t
            float a2 = 0.f;
            for (int e = 0; e < DD; ++e) a2 = fmaf(sxT[e * 64 + t], swq[e * 68 + 64], a2);
            sv[t * 68 + 64] = gelu_exact(a2 + sb[64]) + pos[t * DD + 64];
        }
    }
    __syncthreads();

    // ---- load q transposed into swq: qT[dd][k] ----
    const float* qb = g_q + (size_t)b * KK * DD;
    for (int i = t; i < KK * DD; i += 256) { int k = i / DD, dd = i - k * DD; swq[dd * 68 + k] = qb[i]; }
    __syncthreads();

    // ---- scores[k][c] = SCALE * sum_dd qT[dd][k] * skT[dd][c] ----
    {
        int k0 = ty * 4, c0 = tx * 4;
        u64 acc2[2][4] = {};
        #pragma unroll 4
        for (int dd = 0; dd < DD; ++dd) {
            float4 a = *(const float4*)(swq + dd * 68 + k0);  // qT[dd][k0..]
            float4 w = *(const float4*)(skT + dd * 64 + c0);  // keysT[dd][c0..]
            u64 a01 = pack2(a.x, a.y), a23 = pack2(a.z, a.w);
            u64 w0 = dup2(w.x), w1 = dup2(w.y), w2 = dup2(w.z), w3 = dup2(w.w);
            acc2[0][0] = fma2(a01, w0, acc2[0][0]); acc2[0][1] = fma2(a01, w1, acc2[0][1]);
            acc2[0][2] = fma2(a01, w2, acc2[0][2]); acc2[0][3] = fma2(a01, w3, acc2[0][3]);
            acc2[1][0] = fma2(a23, w0, acc2[1][0]); acc2[1][1] = fma2(a23, w1, acc2[1][1]);
            acc2[1][2] = fma2(a23, w2, acc2[1][2]); acc2[1][3] = fma2(a23, w3, acc2[1][3]);
        }
        #pragma unroll
        for (int ip = 0; ip < 2; ++ip) {
            int k_0 = k0 + ip * 2, k_1 = k_0 + 1;
            #pragma unroll
            for (int j = 0; j < 4; ++j) {
                float2 p = unpk(acc2[ip][j]);
                ss[k_0 * 68 + c0 + j] = p.x * SCALE;
                ss[k_1 * 68 + c0 + j] = p.y * SCALE;
            }
        }
    }
    __syncthreads();

    // ---- softmax over c (in place, warp per row) ----
    for (int row = warp; row < KK; row += 8) {
        float v0 = ss[row * 68 + lane], v1 = ss[row * 68 + lane + 32];
        float m = fmaxf(v0, v1);
        #pragma unroll
        for (int o = 16; o > 0; o >>= 1) m = fmaxf(m, __shfl_xor_sync(0xffffffffu, m, o));
        float e0 = __expf(v0 - m), e1 = __expf(v1 - m);
        float s = e0 + e1;
        #pragma unroll
        for (int o = 16; o > 0; o >>= 1) s += __shfl_xor_sync(0xffffffffu, s, o);
        float inv = 1.0f / s;
        ss[row * 68 + lane] = e0 * inv;
        ss[row * 68 + lane + 32] = e1 * inv;
    }
    __syncthreads();

    // ---- blk[k][dd] = sum_c prob[k][c] * sv[c][dd] -> g_blk[b][k][chunk][dd] ----
    {
        int k0 = ty * 4, d0 = tx * 4;
        u64 acc2[2][4] = {};
        #pragma unroll 4
        for (int c = 0; c < CH; ++c) {
            float a0 = ss[(k0 + 0) * 68 + c], a1 = ss[(k0 + 1) * 68 + c];
            float a2 = ss[(k0 + 2) * 68 + c], a3 = ss[(k0 + 3) * 68 + c];
            u64 a01 = pack2(a0, a1), a23 = pack2(a2, a3);
            float4 v = *(const float4*)(sv + c * 68 + d0);
            u64 w0 = dup2(v.x), w1 = dup2(v.y), w2 = dup2(v.z), w3 = dup2(v.w);
            acc2[0][0] = fma2(a01, w0, acc2[0][0]); acc2[0][1] = fma2(a01, w1, acc2[0][1]);
            acc2[0][2] = fma2(a01, w2, acc2[0][2]); acc2[0][3] = fma2(a01, w3, acc2[0][3]);
            acc2[1][0] = fma2(a23, w0, acc2[1][0]); acc2[1][1] = fma2(a23, w1, acc2[1][1]);
            acc2[1][2] = fma2(a23, w2, acc2[1][2]); acc2[1][3] = fma2(a23, w3, acc2[1][3]);
        }
        #pragma unroll
        for (int ip = 0; ip < 2; ++ip) {
            int kk0 = k0 + ip * 2, kk1 = kk0 + 1;
            size_t base0 = ((size_t)(b * KK + kk0) * NBL + chunk) * DD + d0;
            size_t base1 = ((size_t)(b * KK + kk1) * NBL + chunk) * DD + d0;
            #pragma unroll
            for (int j = 0; j < 4; ++j) {
                float2 p = unpk(acc2[ip][j]);
                g_blk[base0 + j] = p.x;
                g_blk[base1 + j] = p.y;
            }
        }
        if (t < KK) {  // dd = 64 tail, k = t
            float a2 = 0.f;
            for (int c = 0; c < CH; ++c) a2 = fmaf(ss[t * 68 + c], sv[c * 68 + 64], a2);
            g_blk[((size_t)(b * KK + t) * NBL + chunk) * DD + 64] = a2;
        }
    }
}

// ================= Kernel D: cross-block attention + residual + LayerNorm =================
// grid (B*K), 256 threads, 3 CTAs/SM. Smem: sblk 16640 | scs 256 | scq 68 | swr 8 | scomp 132 | sfin 2
#define KD_SMEM_FLOATS (16640 + 256 + 68 + 8 + 132 + 2)

__global__ __launch_bounds__(256, 3) void kD(
    const float* __restrict__ cq, const float* __restrict__ gamma,
    const float* __restrict__ beta, float* __restrict__ out) {
    extern __shared__ float sm[];
    float* sblk  = sm;
    float* scs   = sm + 16640;
    float* scq   = scs + 256;
    float* swr   = scq + 68;
    float* scomp = swr + 8;
    float* sfin  = scomp + 132;

    int t = threadIdx.x, warp = t >> 5, lane = t & 31;
    int bk = blockIdx.x;                 // = b*K + k
    int b = bk / KK;

    // vectorized stage of blk[b][k] (16640 floats = 4160 float4)
    const float4* src4 = (const float4*)(g_blk + (size_t)bk * NBL * DD);
    float4* sblk4 = (float4*)sblk;
    #pragma unroll 4
    for (int i = t; i < (NBL * DD) / 4; i += 256) sblk4[i] = src4[i];
    if (t < DD) scq[t] = cq[t];
    __syncthreads();

    // cs[n] = SCALE * cross_q . blk[n,:]
    for (int n = warp; n < NBL; n += 8) {
        const float* row = sblk + n * DD;
        float p = row[lane] * scq[lane] + row[lane + 32] * scq[lane + 32];
        if (lane == 0) p += row[64] * scq[64];
        #pragma unroll
        for (int o = 16; o > 0; o >>= 1) p += __shfl_xor_sync(0xffffffffu, p, o);
        if (lane == 0) scs[n] = p * SCALE;
    }
    __syncthreads();

    // softmax over 256
    float v = scs[t];
    float m = v;
    #pragma unroll
    for (int o = 16; o > 0; o >>= 1) m = fmaxf(m, __shfl_xor_sync(0xffffffffu, m, o));
    if (lane == 0) swr[warp] = m;
    __syncthreads();
    if (t == 0) {
        float mm = swr[0];
        #pragma unroll
        for (int w = 1; w < 8; ++w) mm = fmaxf(mm, swr[w]);
        sfin[0] = mm;
    }
    __syncthreads();
    float e = __expf(v - sfin[0]);
    float s = e;
    #pragma unroll
    for (int o = 16; o > 0; o >>= 1) s += __shfl_xor_sync(0xffffffffu, s, o);
    if (lane == 0) swr[warp] = s;
    __syncthreads();
    if (t == 0) {
        float ts = 0.f;
        #pragma unroll
        for (int w = 0; w < 8; ++w) ts += swr[w];
        sfin[1] = ts;
    }
    __syncthreads();
    scs[t] = e / sfin[1];
    __syncthreads();

    // compressed[d] = sum_n cw[n] * blk[n][d]  (split n into two halves)
    if (t < 2 * DD) {
        int d = t % DD, g = t / DD;
        float a = 0.f;
        int n0 = g * 128;
        for (int n = n0; n < n0 + 128; ++n) a = fmaf(scs[n], sblk[n * DD + d], a);
        scomp[t] = a;
    }
    __syncthreads();
    if (t < DD) scomp[t] = scomp[t] + scomp[DD + t] + g_r[b * DD + t];
    __syncthreads();

    if (t == 0) {
        float mu = 0.f;
        for (int d = 0; d < DD; ++d) mu += scomp[d];
        mu *= (1.0f / DD);
        float var = 0.f;
        for (int d = 0; d < DD; ++d) { float dv = scomp[d] - mu; var += dv * dv; }
        var *= (1.0f / DD);
        sfin[0] = mu;
        sfin[1] = rsqrtf(var + 1e-5f);
    }
    __syncthreads();
    if (t < DD)
        out[(size_t)bk * DD + t] = (scomp[t] - sfin[0]) * sfin[1] * gamma[t] + beta[t];
}

// ================= launch =================
extern "C" void kernel_launch(void* const* d_in, const int* in_sizes, int n_in,
                              void* d_out, int out_size) {
    (void)in_sizes; (void)n_in; (void)out_size;
    const float* x    = (const float*)d_in[0];
    const float* Wq1  = (const float*)d_in[1];
    const float* bq1  = (const float*)d_in[2];
    const float* Wq2  = (const float*)d_in[3];
    const float* bq2  = (const float*)d_in[4];
    const float* Wk   = (const float*)d_in[5];
    const float* bk   = (const float*)d_in[6];
    const float* Wv   = (const float*)d_in[7];
    const float* bv   = (const float*)d_in[8];
    const float* cq   = (const float*)d_in[9];
    const float* pos  = (const float*)d_in[10];
    const float* Wr   = (const float*)d_in[11];
    const float* br   = (const float*)d_in[12];
    const float* gam  = (const float*)d_in[13];
    const float* bet  = (const float*)d_in[14];
    float* out = (float*)d_out;

    cudaFuncSetAttribute(kC, cudaFuncAttributeMaxDynamicSharedMemorySize,
                         KC_SMEM_FLOATS * (int)sizeof(float));
    cudaFuncSetAttribute(kD, cudaFuncAttributeMaxDynamicSharedMemorySize,
                         KD_SMEM_FLOATS * (int)sizeof(float));

    kA<<<dim3(64, BB), 256>>>(x);
    kB<<<dim3(BB, 16), 256>>>(Wq1, bq1, Wq2, bq2, Wr, br);
    kC<<<dim3(NBL, BB), 256, KC_SMEM_FLOATS * sizeof(float)>>>(x, Wk, bk, Wv, bv, pos);
    kD<<<BB * KK, 256, KD_SMEM_FLOATS * sizeof(float)>>>(cq, gam, bet, out);
}

// round 13
// speedup vs baseline: 1.3226x; 1.1871x over previous
#include <cuda_runtime.h>
#include <math.h>

#define BB   32
#define NN   16384
#define DD   65
#define CH   64
#define KK   64
#define NBL  256
#define SCALE 0.1240347345892081f   /* 65^-0.5 */

// ---------------- scratch (device globals: no allocation allowed) ----------------
__device__ float g_partial[BB * 64 * DD];                 // per-(b,split) column sums
__device__ float g_q[BB * KK * DD];                       // queries (SCALE folded in)
__device__ float g_r[BB * DD];                            // gavg@Wr + br
__device__ float g_blk[(size_t)BB * KK * NBL * DD];       // block-attention output, 136 MB

__device__ __forceinline__ float gelu_exact(float v) {
    return 0.5f * v * (1.0f + erff(v * 0.70710678118654752f));
}

// ---- tf32 helpers ----
__device__ __forceinline__ unsigned cvt_tf32(float v) {
    unsigned r; asm("cvt.rna.tf32.f32 %0,%1;" : "=r"(r) : "f"(v)); return r;
}
__device__ __forceinline__ void mma_tf32(float* c,
    unsigned a0, unsigned a1, unsigned a2, unsigned a3,
    unsigned b0, unsigned b1) {
    asm("mma.sync.aligned.m16n8k8.row.col.f32.tf32.tf32.f32 "
        "{%0,%1,%2,%3},{%4,%5,%6,%7},{%8,%9},{%0,%1,%2,%3};"
        : "+f"(c[0]), "+f"(c[1]), "+f"(c[2]), "+f"(c[3])
        : "r"(a0), "r"(a1), "r"(a2), "r"(a3), "r"(b0), "r"(b1));
}

// ================= Kernel A: partial column sums of x over N =================
__global__ void kA(const float* __restrict__ x) {
    int b = blockIdx.y, s = blockIdx.x;
    int warp = threadIdx.x >> 5, lane = threadIdx.x & 31;
    const float* xb = x + ((size_t)b * NN + (size_t)s * 256 + warp * 32) * DD;
    float a0 = 0.f, a1 = 0.f, a2 = 0.f;
    #pragma unroll 4
    for (int r = 0; r < 32; ++r) {
        const float* row = xb + r * DD;
        a0 += row[lane];
        a1 += row[lane + 32];
        if (lane == 0) a2 += row[64];
    }
    __shared__ float sm[8][DD];
    sm[warp][lane] = a0;
    sm[warp][lane + 32] = a1;
    if (lane == 0) sm[warp][64] = a2;
    __syncthreads();
    if (threadIdx.x < DD) {
        float t = 0.f;
        #pragma unroll
        for (int w = 0; w < 8; ++w) t += sm[w][threadIdx.x];
        g_partial[(b * 64 + s) * DD + threadIdx.x] = t;
    }
}

// ================= Kernel B: gavg -> q (scaled), r = gavg@Wr+br =================
__global__ void kB(const float* __restrict__ Wq1, const float* __restrict__ bq1,
                   const float* __restrict__ Wq2, const float* __restrict__ bq2,
                   const float* __restrict__ Wr,  const float* __restrict__ br) {
    int b = blockIdx.x, slice = blockIdx.y;
    __shared__ float gavg[DD], h[DD];
    int t = threadIdx.x;
    if (t < DD) {
        float s = 0.f;
        for (int p = 0; p < 64; ++p) s += g_partial[(b * 64 + p) * DD + t];
        gavg[t] = s * (1.0f / (float)NN);
    }
    __syncthreads();
    if (t < DD) {
        float acc = bq1[t];
        for (int e = 0; e < DD; ++e) acc = fmaf(gavg[e], Wq1[e * DD + t], acc);
        h[t] = gelu_exact(acc);
        if (slice == 0) {
            float r = br[t];
            for (int e = 0; e < DD; ++e) r = fmaf(gavg[e], Wr[e * DD + t], r);
            g_r[b * DD + t] = r;
        }
    }
    __syncthreads();
    int jend = (slice + 1) * 260;
    for (int j = slice * 260 + t; j < jend; j += 256) {
        float acc = bq2[j];
        for (int e = 0; e < DD; ++e) acc = fmaf(h[e], Wq2[e * (KK * DD) + j], acc);
        g_q[b * KK * DD + j] = acc * SCALE;
    }
}

// ================= Kernel C: fused per-chunk block attention (tf32 mma.sync) =================
// grid (NBL, B), 256 threads = 8 warps, dynamic smem 99104 B, 2 CTAs/SM.
// Smem float layout:
//   XS  [64][76] x (tf32, k-pad zero)               off 0      (4864)
//   WB  [72][72] Wk -> Wv (tf32, B-layout) / later ps [64][76] fp32->tf32   off 4864 (5184)
//   KB  [72][72] keysB (tf32, [dd][c])              off 10048  (5184)
//   VB  [64][72] values (tf32, [c][dd])             off 15232  (4608)
//   PQ  [64][76] pos (fp32) -> qs (tf32)            off 19840  (4864)
//   SB  [72]     bias (pad zero)                    off 24704  (72)
#define KC_SMEM_FLOATS 24776
#define OXS 0
#define OWB 4864
#define OKB 10048
#define OVB 15232
#define OPQ 19840
#define OSB 24704

// One warp's share of a GEMM: M-tile m0 (16 rows), N-tiles nbase..nbase+nt-1 (8 cols each),
// KS k-steps of 8.  A row-major ld=la (tf32 bits), B [k][n] ld=lb (tf32 bits).
__device__ __forceinline__ void mma_block(
    const unsigned* __restrict__ A, int la,
    const unsigned* __restrict__ B, int lb,
    int m0, int nbase, int nt, int KS,
    float (&acc)[5][4], int g, int tg) {
    for (int kt = 0; kt < KS; ++kt) {
        int k0 = kt * 8;
        unsigned a0 = A[(m0 + g) * la + k0 + tg];
        unsigned a1 = A[(m0 + g + 8) * la + k0 + tg];
        unsigned a2 = A[(m0 + g) * la + k0 + tg + 4];
        unsigned a3 = A[(m0 + g + 8) * la + k0 + tg + 4];
        #pragma unroll
        for (int i = 0; i < 5; ++i) {
            if (i < nt) {
                int n0 = (nbase + i) * 8;
                unsigned b0 = B[(k0 + tg) * lb + n0 + g];
                unsigned b1 = B[(k0 + tg + 4) * lb + n0 + g];
                mma_tf32(acc[i], a0, a1, a2, a3, b0, b1);
            }
        }
    }
}

__global__ __launch_bounds__(256, 2) void kC(
    const float* __restrict__ x,
    const float* __restrict__ Wk, const float* __restrict__ bk,
    const float* __restrict__ Wv, const float* __restrict__ bv,
    const float* __restrict__ pos) {
    extern __shared__ float sm[];
    unsigned* xsu = (unsigned*)(sm + OXS);
    unsigned* wBu = (unsigned*)(sm + OWB);
    float*    ps  = sm + OWB;                // aliases WB after values GEMM
    unsigned* psu = (unsigned*)(sm + OWB);
    unsigned* kBu = (unsigned*)(sm + OKB);
    unsigned* vBu = (unsigned*)(sm + OVB);
    float*    pqs = sm + OPQ;                // pos (fp32), later q (tf32 bits)
    unsigned* pqu = (unsigned*)(sm + OPQ);
    float*    sb  = sm + OSB;

    int t = threadIdx.x;
    int warp = t >> 5, lane = t & 31;
    int g = lane >> 2, tg = lane & 3;
    int chunk = blockIdx.x, b = blockIdx.y;

    int m0 = (warp >> 1) * 16;
    int even = !(warp & 1);

    // ---- zero padded operand buffers (XS..VB) + bias ----
    {
        float4 z = {0.f, 0.f, 0.f, 0.f};
        float4* p4 = (float4*)sm;
        for (int i = t; i < OPQ / 4; i += 256) p4[i] = z;
        if (t < 72) sb[t] = 0.f;
    }
    __syncthreads();

    // ---- fill: x (tf32), Wk (tf32), pos (fp32), bk ----
    const float* xc = x + ((size_t)b * NN + (size_t)chunk * CH) * DD;
    for (int i = t; i < CH * DD; i += 256) {
        int c = i / DD, e = i - c * DD;
        xsu[c * 76 + e] = cvt_tf32(xc[i]);
    }
    for (int i = t; i < DD * DD; i += 256) {
        int e = i / DD, d = i - e * DD;
        wBu[e * 72 + d] = cvt_tf32(Wk[i]);
    }
    for (int i = t; i < CH * DD; i += 256) {
        int c = i / DD, d = i - c * DD;
        pqs[c * 76 + d] = pos[i];
    }
    if (t < DD) sb[t] = bk[t];
    __syncthreads();

    // ---- keys = gelu(x@Wk + bk) + pos -> keysB[dd][c] (tf32) ----
    {
        float acc[5][4] = {};
        int nt = even ? 5 : 4, nbase = even ? 0 : 5;
        mma_block(xsu, 76, wBu, 72, m0, nbase, nt, 9, acc, g, tg);
        int r0 = m0 + g, r1 = r0 + 8;
        #pragma unroll
        for (int i = 0; i < 5; ++i) if (i < nt) {
            int d0 = (nbase + i) * 8 + 2 * tg;
            #pragma unroll
            for (int e2 = 0; e2 < 2; ++e2) {
                int d = d0 + e2;
                if (d < DD) {
                    float v0 = gelu_exact(acc[i][e2] + sb[d]) + pqs[r0 * 76 + d];
                    float v1 = gelu_exact(acc[i][2 + e2] + sb[d]) + pqs[r1 * 76 + d];
                    kBu[d * 72 + r0] = cvt_tf32(v0);
                    kBu[d * 72 + r1] = cvt_tf32(v1);
                }
            }
        }
    }
    __syncthreads();

    // ---- swap weights: Wv, bv ----
    for (int i = t; i < DD * DD; i += 256) {
        int e = i / DD, d = i - e * DD;
        wBu[e * 72 + d] = cvt_tf32(Wv[i]);
    }
    if (t < DD) sb[t] = bv[t];
    __syncthreads();

    // ---- values = gelu(x@Wv + bv) + pos -> vB[c][dd] (tf32) ----
    {
        float acc[5][4] = {};
        int nt = even ? 5 : 4, nbase = even ? 0 : 5;
        mma_block(xsu, 76, wBu, 72, m0, nbase, nt, 9, acc, g, tg);
        int r0 = m0 + g, r1 = r0 + 8;
        #pragma unroll
        for (int i = 0; i < 5; ++i) if (i < nt) {
            int d0 = (nbase + i) * 8 + 2 * tg;
            #pragma unroll
            for (int e2 = 0; e2 < 2; ++e2) {
                int d = d0 + e2;
                if (d < DD) {
                    float v0 = gelu_exact(acc[i][e2] + sb[d]) + pqs[r0 * 76 + d];
                    float v1 = gelu_exact(acc[i][2 + e2] + sb[d]) + pqs[r1 * 76 + d];
                    vBu[r0 * 72 + d] = cvt_tf32(v0);
                    vBu[r1 * 72 + d] = cvt_tf32(v1);
                }
            }
        }
    }
    __syncthreads();

    // ---- overwrite pos with q (tf32, SCALE pre-folded), zero k-pad ----
    {
        const float* qb = g_q + (size_t)b * KK * DD;
        for (int i = t; i < KK * 76; i += 256) {
            int k = i / 76, d = i - k * 76;
            pqu[i] = (d < DD) ? cvt_tf32(qb[k * DD + d]) : 0u;
        }
    }
    __syncthreads();

    // ---- scores[kq][c] = SCALE * q @ keysB  -> ps fp32 (ld 76) ----
    {
        float acc[5][4] = {};
        int nbase = even ? 0 : 4;
        mma_block(pqu, 76, kBu, 72, m0, nbase, 4, 9, acc, g, tg);
        int r0 = m0 + g, r1 = r0 + 8;
        #pragma unroll
        for (int i = 0; i < 4; ++i) {
            int c0 = (nbase + i) * 8 + 2 * tg;
            #pragma unroll
            for (int e2 = 0; e2 < 2; ++e2) {
                ps[r0 * 76 + c0 + e2] = acc[i][e2] * SCALE;
                ps[r1 * 76 + c0 + e2] = acc[i][2 + e2] * SCALE;
            }
        }
    }
    __syncthreads();

    // ---- softmax rows of ps, store back as tf32 ----
    for (int row = warp; row < KK; row += 8) {
        float v0 = ps[row * 76 + lane], v1 = ps[row * 76 + lane + 32];
        float m = fmaxf(v0, v1);
        #pragma unroll
        for (int o = 16; o > 0; o >>= 1) m = fmaxf(m, __shfl_xor_sync(0xffffffffu, m, o));
        float e0 = __expf(v0 - m), e1 = __expf(v1 - m);
        float s = e0 + e1;
        #pragma unroll
        for (int o = 16; o > 0; o >>= 1) s += __shfl_xor_sync(0xffffffffu, s, o);
        float inv = 1.0f / s;
        psu[row * 76 + lane] = cvt_tf32(e0 * inv);
        psu[row * 76 + lane + 32] = cvt_tf32(e1 * inv);
    }
    __syncthreads();

    // ---- blk[kq][dd] = P @ V -> g_blk[b][kq][chunk][dd] ----
    {
        float acc[5][4] = {};
        int nt = even ? 5 : 4, nbase = even ? 0 : 5;
        mma_block(psu, 76, vBu, 72, m0, nbase, nt, 8, acc, g, tg);
        int r0 = m0 + g, r1 = r0 + 8;
        size_t base0 = ((size_t)(b * KK + r0) * NBL + chunk) * DD;
        size_t base1 = ((size_t)(b * KK + r1) * NBL + chunk) * DD;
        #pragma unroll
        for (int i = 0; i < 5; ++i) if (i < nt) {
            int d0 = (nbase + i) * 8 + 2 * tg;
            #pragma unroll
            for (int e2 = 0; e2 < 2; ++e2) {
                int d = d0 + e2;
                if (d < DD) {
                    g_blk[base0 + d] = acc[i][e2];
                    g_blk[base1 + d] = acc[i][2 + e2];
                }
            }
        }
    }
}

// ================= Kernel D: cross-block attention + residual + LayerNorm =================
// grid (B*K), 256 threads, 3 CTAs/SM. Smem: sblk 16640 | scs 256 | scq 68 | swr 8 | scomp 132 | sfin 2
#define KD_SMEM_FLOATS (16640 + 256 + 68 + 8 + 132 + 2)

__global__ __launch_bounds__(256, 3) void kD(
    const float* __restrict__ cq, const float* __restrict__ gamma,
    const float* __restrict__ beta, float* __restrict__ out) {
    extern __shared__ float sm[];
    float* sblk  = sm;
    float* scs   = sm + 16640;
    float* scq   = scs + 256;
    float* swr   = scq + 68;
    float* scomp = swr + 8;
    float* sfin  = scomp + 132;

    int t = threadIdx.x, warp = t >> 5, lane = t & 31;
    int bk = blockIdx.x;                 // = b*K + k
    int b = bk / KK;

    const float4* src4 = (const float4*)(g_blk + (size_t)bk * NBL * DD);
    float4* sblk4 = (float4*)sblk;
    #pragma unroll 4
    for (int i = t; i < (NBL * DD) / 4; i += 256) sblk4[i] = src4[i];
    if (t < DD) scq[t] = cq[t];
    __syncthreads();

    for (int n = warp; n < NBL; n += 8) {
        const float* row = sblk + n * DD;
        float p = row[lane] * scq[lane] + row[lane + 32] * scq[lane + 32];
        if (lane == 0) p += row[64] * scq[64];
        #pragma unroll
        for (int o = 16; o > 0; o >>= 1) p += __shfl_xor_sync(0xffffffffu, p, o);
        if (lane == 0) scs[n] = p * SCALE;
    }
    __syncthreads();

    float v = scs[t];
    float m = v;
    #pragma unroll
    for (int o = 16; o > 0; o >>= 1) m = fmaxf(m, __shfl_xor_sync(0xffffffffu, m, o));
    if (lane == 0) swr[warp] = m;
    __syncthreads();
    if (t == 0) {
        float mm = swr[0];
        #pragma unroll
        for (int w = 1; w < 8; ++w) mm = fmaxf(mm, swr[w]);
        sfin[0] = mm;
    }
    __syncthreads();
    float e = __expf(v - sfin[0]);
    float s = e;
    #pragma unroll
    for (int o = 16; o > 0; o >>= 1) s += __shfl_xor_sync(0xffffffffu, s, o);
    if (lane == 0) swr[warp] = s;
    __syncthreads();
    if (t == 0) {
        float ts = 0.f;
        #pragma unroll
        for (int w = 0; w < 8; ++w) ts += swr[w];
        sfin[1] = ts;
    }
    __syncthreads();
    scs[t] = e / sfin[1];
    __syncthreads();

    if (t < 2 * DD) {
        int d = t % DD, gg = t / DD;
        float a = 0.f;
        int n0 = gg * 128;
        for (int n = n0; n < n0 + 128; ++n) a = fmaf(scs[n], sblk[n * DD + d], a);
        scomp[t] = a;
    }
    __syncthreads();
    if (t < DD) scomp[t] = scomp[t] + scomp[DD + t] + g_r[b * DD + t];
    __syncthreads();

    if (t == 0) {
        float mu = 0.f;
        for (int d = 0; d < DD; ++d) mu += scomp[d];
        mu *= (1.0f / DD);
        float var = 0.f;
        for (int d = 0; d < DD; ++d) { float dv = scomp[d] - mu; var += dv * dv; }
        var *= (1.0f / DD);
        sfin[0] = mu;
        sfin[1] = rsqrtf(var + 1e-5f);
    }
    __syncthreads();
    if (t < DD)
        out[(size_t)bk * DD + t] = (scomp[t] - sfin[0]) * sfin[1] * gamma[t] + beta[t];
}

// ================= launch =================
extern "C" void kernel_launch(void* const* d_in, const int* in_sizes, int n_in,
                              void* d_out, int out_size) {
    (void)in_sizes; (void)n_in; (void)out_size;
    const float* x    = (const float*)d_in[0];
    const float* Wq1  = (const float*)d_in[1];
    const float* bq1  = (const float*)d_in[2];
    const float* Wq2  = (const float*)d_in[3];
    const float* bq2  = (const float*)d_in[4];
    const float* Wk   = (const float*)d_in[5];
    const float* bk   = (const float*)d_in[6];
    const float* Wv   = (const float*)d_in[7];
    const float* bv   = (const float*)d_in[8];
    const float* cq   = (const float*)d_in[9];
    const float* pos  = (const float*)d_in[10];
    const float* Wr   = (const float*)d_in[11];
    const float* br   = (const float*)d_in[12];
    const float* gam  = (const float*)d_in[13];
    const float* bet  = (const float*)d_in[14];
    float* out = (float*)d_out;

    cudaFuncSetAttribute(kC, cudaFuncAttributeMaxDynamicSharedMemorySize,
                         KC_SMEM_FLOATS * (int)sizeof(float));
    cudaFuncSetAttribute(kD, cudaFuncAttributeMaxDynamicSharedMemorySize,
                         KD_SMEM_FLOATS * (int)sizeof(float));

    kA<<<dim3(64, BB), 256>>>(x);
    kB<<<dim3(BB, 16), 256>>>(Wq1, bq1, Wq2, bq2, Wr, br);
    kC<<<dim3(NBL, BB), 256, KC_SMEM_FLOATS * sizeof(float)>>>(x, Wk, bk, Wv, bv, pos);
    kD<<<BB * KK, 256, KD_SMEM_FLOATS * sizeof(float)>>>(cq, gam, bet, out);
}

// round 14
// speedup vs baseline: 2.1804x; 1.6486x over previous
#include <cuda_runtime.h>
#include <math.h>

#define BB   32
#define NN   16384
#define DD   65
#define CH   64
#define KK   64
#define NBL  256
#define NCHU 4
#define SCALE 0.1240347345892081f   /* 65^-0.5 */

// ---------------- scratch (device globals: no allocation allowed) ----------------
__device__ float g_partial[BB * 64 * DD];                 // per-(b,split) column sums
__device__ float g_q[BB * KK * DD];                       // queries (SCALE folded in)
__device__ float g_r[BB * DD];                            // gavg@Wr + br
__device__ float g_blk[(size_t)BB * KK * NBL * DD];       // block-attention output, 136 MB

__device__ __forceinline__ float gelu_exact(float v) {
    return 0.5f * v * (1.0f + erff(v * 0.70710678118654752f));
}

// ---- tf32 helpers ----
__device__ __forceinline__ unsigned cvt_tf32(float v) {
    unsigned r; asm("cvt.rna.tf32.f32 %0,%1;" : "=r"(r) : "f"(v)); return r;
}
__device__ __forceinline__ void mma_tf32(float* c,
    unsigned a0, unsigned a1, unsigned a2, unsigned a3,
    unsigned b0, unsigned b1) {
    asm("mma.sync.aligned.m16n8k8.row.col.f32.tf32.tf32.f32 "
        "{%0,%1,%2,%3},{%4,%5,%6,%7},{%8,%9},{%0,%1,%2,%3};"
        : "+f"(c[0]), "+f"(c[1]), "+f"(c[2]), "+f"(c[3])
        : "r"(a0), "r"(a1), "r"(a2), "r"(a3), "r"(b0), "r"(b1));
}

// ================= Kernel A: partial column sums of x over N =================
__global__ void kA(const float* __restrict__ x) {
    int b = blockIdx.y, s = blockIdx.x;
    int warp = threadIdx.x >> 5, lane = threadIdx.x & 31;
    const float* xb = x + ((size_t)b * NN + (size_t)s * 256 + warp * 32) * DD;
    float a0 = 0.f, a1 = 0.f, a2 = 0.f;
    #pragma unroll 4
    for (int r = 0; r < 32; ++r) {
        const float* row = xb + r * DD;
        a0 += row[lane];
        a1 += row[lane + 32];
        if (lane == 0) a2 += row[64];
    }
    __shared__ float sm[8][DD];
    sm[warp][lane] = a0;
    sm[warp][lane + 32] = a1;
    if (lane == 0) sm[warp][64] = a2;
    __syncthreads();
    if (threadIdx.x < DD) {
        float t = 0.f;
        #pragma unroll
        for (int w = 0; w < 8; ++w) t += sm[w][threadIdx.x];
        g_partial[(b * 64 + s) * DD + threadIdx.x] = t;
    }
}

// ================= Kernel B: gavg -> q (scaled), r = gavg@Wr+br =================
__global__ void kB(const float* __restrict__ Wq1, const float* __restrict__ bq1,
                   const float* __restrict__ Wq2, const float* __restrict__ bq2,
                   const float* __restrict__ Wr,  const float* __restrict__ br) {
    int b = blockIdx.x, slice = blockIdx.y;
    __shared__ float gavg[DD], h[DD];
    int t = threadIdx.x;
    if (t < DD) {
        float s = 0.f;
        for (int p = 0; p < 64; ++p) s += g_partial[(b * 64 + p) * DD + t];
        gavg[t] = s * (1.0f / (float)NN);
    }
    __syncthreads();
    if (t < DD) {
        float acc = bq1[t];
        for (int e = 0; e < DD; ++e) acc = fmaf(gavg[e], Wq1[e * DD + t], acc);
        h[t] = gelu_exact(acc);
        if (slice == 0) {
            float r = br[t];
            for (int e = 0; e < DD; ++e) r = fmaf(gavg[e], Wr[e * DD + t], r);
            g_r[b * DD + t] = r;
        }
    }
    __syncthreads();
    int jend = (slice + 1) * 260;
    for (int j = slice * 260 + t; j < jend; j += 256) {
        float acc = bq2[j];
        for (int e = 0; e < DD; ++e) acc = fmaf(h[e], Wq2[e * (KK * DD) + j], acc);
        g_q[b * KK * DD + j] = acc * SCALE;
    }
}

// ================= Kernel C: fused block attention, 4 chunks/CTA (tf32 mma) ==========
// grid (NBL/NCHU, B), 512 threads = 16 warps, 129472 B dynamic smem, 1 CTA/SM.
// Smem float layout (all GEMMs KS=8; k=64 handled by exact fp32 correction):
//   X/PS [64][68]  x tf32  -> probs tf32 (aliased)   off 0      (4352)
//   WKV  [65][152] Wk cols 0..64 | Wv cols 72..136   off 4352   (9880)
//   QT   [64][68]  q tf32 (SCALE folded)             off 14232  (4352)
//   KB   [65][72]  keys^T tf32 [d][c]                off 18584  (4680)
//   VB   [64][72]  values tf32 [c][d]                off 23264  (4608)
//   POS  [64][68]  pos fp32                          off 27872  (4352)
//   SB   [144]     bias per WKV col                  off 32224  (144)
#define KC_SMEM_FLOATS 32368
#define OX   0
#define OWKV 4352
#define OQT  14232
#define OKB  18584
#define OVB  23264
#define OPOS 27872
#define OSB  32224

__device__ __forceinline__ void mma_blk8(
    const unsigned* __restrict__ A, int la,
    const unsigned* __restrict__ B, int lb,
    int m0, int nbase, int nt,
    float (&acc)[5][4], int g, int tg) {
    #pragma unroll
    for (int kt = 0; kt < 8; ++kt) {
        int k0 = kt * 8;
        unsigned a0 = A[(m0 + g) * la + k0 + tg];
        unsigned a1 = A[(m0 + g + 8) * la + k0 + tg];
        unsigned a2 = A[(m0 + g) * la + k0 + tg + 4];
        unsigned a3 = A[(m0 + g + 8) * la + k0 + tg + 4];
        #pragma unroll
        for (int i = 0; i < 5; ++i) {
            if (i < nt) {
                int n0 = (nbase + i) * 8;
                unsigned b0 = B[(k0 + tg) * lb + n0 + g];
                unsigned b1 = B[(k0 + tg + 4) * lb + n0 + g];
                mma_tf32(acc[i], a0, a1, a2, a3, b0, b1);
            }
        }
    }
}

__global__ __launch_bounds__(512, 1) void kC(
    const float* __restrict__ x,
    const float* __restrict__ Wk, const float* __restrict__ bk,
    const float* __restrict__ Wv, const float* __restrict__ bv,
    const float* __restrict__ pos) {
    extern __shared__ float sm[];
    unsigned* xsu  = (unsigned*)(sm + OX);
    float*    xsf  = sm + OX;
    float*    ps   = sm + OX;                 // probs alias X (X dead after KV GEMM)
    unsigned* psu  = (unsigned*)(sm + OX);
    unsigned* wkvu = (unsigned*)(sm + OWKV);
    float*    wkvf = sm + OWKV;
    unsigned* qtu  = (unsigned*)(sm + OQT);
    float*    qtf  = sm + OQT;
    unsigned* kBu  = (unsigned*)(sm + OKB);
    float*    kBf  = sm + OKB;
    unsigned* vBu  = (unsigned*)(sm + OVB);
    float*    pqs  = sm + OPOS;
    float*    sb   = sm + OSB;

    int t = threadIdx.x;
    int warp = t >> 5, lane = t & 31;
    int g = lane >> 2, tg = lane & 3;
    int wm = warp >> 2, wn = warp & 3;
    int m0 = wm * 16;
    int b = blockIdx.y;
    int ch0 = blockIdx.x * NCHU;

    // ---- one-time fills: WKV (tf32), QT (tf32), POS (fp32), SB ----
    for (int i = t; i < 65 * 130; i += 512) {
        int e = i / 130, j = i - e * 130;
        int col = (j < 65) ? j : (j + 7);
        float v = (j < 65) ? Wk[e * DD + j] : Wv[e * DD + (j - 65)];
        wkvu[e * 152 + col] = cvt_tf32(v);
    }
    {
        const float* qb = g_q + (size_t)b * KK * DD;
        for (int i = t; i < KK * DD; i += 512) {
            int k = i / DD, d = i - k * DD;
            qtu[k * 68 + d] = cvt_tf32(qb[i]);
        }
    }
    for (int i = t; i < CH * DD; i += 512) {
        int c = i / DD, d = i - c * DD;
        pqs[c * 68 + d] = pos[i];
    }
    if (t < DD) { sb[t] = bk[t]; sb[72 + t] = bv[t]; }

    // ---- prefetch chunk 0's x into registers ----
    float xr[9];
    {
        const float* xb0 = x + ((size_t)b * NN + (size_t)ch0 * CH) * DD;
        #pragma unroll
        for (int p = 0; p < 9; ++p) {
            int i = t + p * 512;
            xr[p] = (i < CH * DD) ? xb0[i] : 0.f;
        }
    }

    for (int ch = 0; ch < NCHU; ++ch) {
        int chunk = ch0 + ch;

        // ---- store prefetched x (tf32) into X ----
        #pragma unroll
        for (int p = 0; p < 9; ++p) {
            int i = t + p * 512;
            if (i < CH * DD) {
                int c = i / DD, e = i - c * DD;
                xsu[c * 68 + e] = cvt_tf32(xr[p]);
            }
        }
        __syncthreads();

        // ---- fused keys|values GEMM: [64x65] @ [65x(65|65)] ----
        {
            float acc[5][4] = {};
            int nbase = (wn == 0) ? 0 : (wn == 1) ? 5 : (wn == 2) ? 9 : 14;
            int nt = (wn & 1) ? 4 : 5;
            mma_blk8(xsu, 68, wkvu, 152, m0, nbase, nt, acc, g, tg);
            int r0 = m0 + g, r1 = r0 + 8;
            float x64_0 = xsf[r0 * 68 + 64], x64_1 = xsf[r1 * 68 + 64];
            #pragma unroll
            for (int i = 0; i < 5; ++i) if (i < nt) {
                int n0 = (nbase + i) * 8;
                #pragma unroll
                for (int e2 = 0; e2 < 2; ++e2) {
                    int col = n0 + 2 * tg + e2;
                    float w64 = wkvf[64 * 152 + col];
                    float a0v = fmaf(x64_0, w64, acc[i][e2]);
                    float a1v = fmaf(x64_1, w64, acc[i][2 + e2]);
                    float bi = sb[col];
                    if (col <= 64) {            // keys, d = col
                        int d = col;
                        float v0 = gelu_exact(a0v + bi) + pqs[r0 * 68 + d];
                        float v1 = gelu_exact(a1v + bi) + pqs[r1 * 68 + d];
                        kBu[d * 72 + r0] = cvt_tf32(v0);
                        kBu[d * 72 + r1] = cvt_tf32(v1);
                    } else if (col >= 72 && col <= 136) {   // values, d = col-72
                        int d = col - 72;
                        float v0 = gelu_exact(a0v + bi) + pqs[r0 * 68 + d];
                        float v1 = gelu_exact(a1v + bi) + pqs[r1 * 68 + d];
                        vBu[r0 * 72 + d] = cvt_tf32(v0);
                        vBu[r1 * 72 + d] = cvt_tf32(v1);
                    }
                }
            }
        }
        __syncthreads();

        // ---- prefetch next chunk's x (latency hidden behind scores/softmax/PV) ----
        if (ch + 1 < NCHU) {
            const float* xn = x + ((size_t)b * NN + (size_t)(chunk + 1) * CH) * DD;
            #pragma unroll
            for (int p = 0; p < 9; ++p) {
                int i = t + p * 512;
                xr[p] = (i < CH * DD) ? xn[i] : 0.f;
            }
        }

        // ---- scores[kq][c] = SCALE * (q @ keys^T) -> PS fp32 ----
        {
            float acc[5][4] = {};
            int nbase = wn * 2;
            mma_blk8(qtu, 68, kBu, 72, m0, nbase, 2, acc, g, tg);
            int r0 = m0 + g, r1 = r0 + 8;
            float q64_0 = qtf[r0 * 68 + 64], q64_1 = qtf[r1 * 68 + 64];
            #pragma unroll
            for (int i = 0; i < 2; ++i) {
                int n0 = (nbase + i) * 8;
                #pragma unroll
                for (int e2 = 0; e2 < 2; ++e2) {
                    int c = n0 + 2 * tg + e2;
                    float k64 = kBf[64 * 72 + c];
                    ps[r0 * 68 + c] = fmaf(q64_0, k64, acc[i][e2]) * SCALE;
                    ps[r1 * 68 + c] = fmaf(q64_1, k64, acc[i][2 + e2]) * SCALE;
                }
            }
        }
        __syncthreads();

        // ---- softmax rows of PS (16 warps x 4 rows), store tf32 ----
        for (int row = warp; row < KK; row += 16) {
            float v0 = ps[row * 68 + lane], v1 = ps[row * 68 + lane + 32];
            float m = fmaxf(v0, v1);
            #pragma unroll
            for (int o = 16; o > 0; o >>= 1) m = fmaxf(m, __shfl_xor_sync(0xffffffffu, m, o));
            float e0 = __expf(v0 - m), e1 = __expf(v1 - m);
            float s = e0 + e1;
            #pragma unroll
            for (int o = 16; o > 0; o >>= 1) s += __shfl_xor_sync(0xffffffffu, s, o);
            float inv = 1.0f / s;
            psu[row * 68 + lane] = cvt_tf32(e0 * inv);
            psu[row * 68 + lane + 32] = cvt_tf32(e1 * inv);
        }
        __syncthreads();

        // ---- blk = P @ V -> g_blk[b][kq][chunk][d] ----
        {
            float acc[5][4] = {};
            int nbase = (wn == 0) ? 0 : (wn == 1) ? 3 : (wn == 2) ? 5 : 7;
            int nt = (wn == 0) ? 3 : 2;
            mma_blk8(psu, 68, vBu, 72, m0, nbase, nt, acc, g, tg);
            int r0 = m0 + g, r1 = r0 + 8;
            size_t base0 = ((size_t)(b * KK + r0) * NBL + chunk) * DD;
            size_t base1 = ((size_t)(b * KK + r1) * NBL + chunk) * DD;
            #pragma unroll
            for (int i = 0; i < 3; ++i) if (i < nt) {
                int n0 = (nbase + i) * 8;
                #pragma unroll
                for (int e2 = 0; e2 < 2; ++e2) {
                    int d = n0 + 2 * tg + e2;
                    if (d < DD) {
                        g_blk[base0 + d] = acc[i][e2];
                        g_blk[base1 + d] = acc[i][2 + e2];
                    }
                }
            }
        }
        __syncthreads();
    }
}

// ================= Kernel D: cross-block attention + residual + LayerNorm =================
// grid (B*K), 256 threads, 3 CTAs/SM. Smem: sblk 16640 | scs 256 | scq 68 | swr 8 | scomp 132 | sfin 2
#define KD_SMEM_FLOATS (16640 + 256 + 68 + 8 + 132 + 2)

__global__ __launch_bounds__(256, 3) void kD(
    const float* __restrict__ cq, const float* __restrict__ gamma,
    const float* __restrict__ beta, float* __restrict__ out) {
    extern __shared__ float sm[];
    float* sblk  = sm;
    float* scs   = sm + 16640;
    float* scq   = scs + 256;
    float* swr   = scq + 68;
    float* scomp = swr + 8;
    float* sfin  = scomp + 132;

    int t = threadIdx.x, warp = t >> 5, lane = t & 31;
    int bk = blockIdx.x;                 // = b*K + k
    int b = bk / KK;

    const float4* src4 = (const float4*)(g_blk + (size_t)bk * NBL * DD);
    float4* sblk4 = (float4*)sblk;
    #pragma unroll 4
    for (int i = t; i < (NBL * DD) / 4; i += 256) sblk4[i] = src4[i];
    if (t < DD) scq[t] = cq[t];
    __syncthreads();

    for (int n = warp; n < NBL; n += 8) {
        const float* row = sblk + n * DD;
        float p = row[lane] * scq[lane] + row[lane + 32] * scq[lane + 32];
        if (lane == 0) p += row[64] * scq[64];
        #pragma unroll
        for (int o = 16; o > 0; o >>= 1) p += __shfl_xor_sync(0xffffffffu, p, o);
        if (lane == 0) scs[n] = p * SCALE;
    }
    __syncthreads();

    float v = scs[t];
    float m = v;
    #pragma unroll
    for (int o = 16; o > 0; o >>= 1) m = fmaxf(m, __shfl_xor_sync(0xffffffffu, m, o));
    if (lane == 0) swr[warp] = m;
    __syncthreads();
    if (t == 0) {
        float mm = swr[0];
        #pragma unroll
        for (int w = 1; w < 8; ++w) mm = fmaxf(mm, swr[w]);
        sfin[0] = mm;
    }
    __syncthreads();
    float e = __expf(v - sfin[0]);
    float s = e;
    #pragma unroll
    for (int o = 16; o > 0; o >>= 1) s += __shfl_xor_sync(0xffffffffu, s, o);
    if (lane == 0) swr[warp] = s;
    __syncthreads();
    if (t == 0) {
        float ts = 0.f;
        #pragma unroll
        for (int w = 0; w < 8; ++w) ts += swr[w];
        sfin[1] = ts;
    }
    __syncthreads();
    scs[t] = e / sfin[1];
    __syncthreads();

    if (t < 2 * DD) {
        int d = t % DD, gg = t / DD;
        float a = 0.f;
        int n0 = gg * 128;
        for (int n = n0; n < n0 + 128; ++n) a = fmaf(scs[n], sblk[n * DD + d], a);
        scomp[t] = a;
    }
    __syncthreads();
    if (t < DD) scomp[t] = scomp[t] + scomp[DD + t] + g_r[b * DD + t];
    __syncthreads();

    if (t == 0) {
        float mu = 0.f;
        for (int d = 0; d < DD; ++d) mu += scomp[d];
        mu *= (1.0f / DD);
        float var = 0.f;
        for (int d = 0; d < DD; ++d) { float dv = scomp[d] - mu; var += dv * dv; }
        var *= (1.0f / DD);
        sfin[0] = mu;
        sfin[1] = rsqrtf(var + 1e-5f);
    }
    __syncthreads();
    if (t < DD)
        out[(size_t)bk * DD + t] = (scomp[t] - sfin[0]) * sfin[1] * gamma[t] + beta[t];
}

// ================= launch =================
extern "C" void kernel_launch(void* const* d_in, const int* in_sizes, int n_in,
                              void* d_out, int out_size) {
    (void)in_sizes; (void)n_in; (void)out_size;
    const float* x    = (const float*)d_in[0];
    const float* Wq1  = (const float*)d_in[1];
    const float* bq1  = (const float*)d_in[2];
    const float* Wq2  = (const float*)d_in[3];
    const float* bq2  = (const float*)d_in[4];
    const float* Wk   = (const float*)d_in[5];
    const float* bk   = (const float*)d_in[6];
    const float* Wv   = (const float*)d_in[7];
    const float* bv   = (const float*)d_in[8];
    const float* cq   = (const float*)d_in[9];
    const float* pos  = (const float*)d_in[10];
    const float* Wr   = (const float*)d_in[11];
    const float* br   = (const float*)d_in[12];
    const float* gam  = (const float*)d_in[13];
    const float* bet  = (const float*)d_in[14];
    float* out = (float*)d_out;

    cudaFuncSetAttribute(kC, cudaFuncAttributeMaxDynamicSharedMemorySize,
                         KC_SMEM_FLOATS * (int)sizeof(float));
    cudaFuncSetAttribute(kD, cudaFuncAttributeMaxDynamicSharedMemorySize,
                         KD_SMEM_FLOATS * (int)sizeof(float));

    kA<<<dim3(64, BB), 256>>>(x);
    kB<<<dim3(BB, 16), 256>>>(Wq1, bq1, Wq2, bq2, Wr, br);
    kC<<<dim3(NBL / NCHU, BB), 512, KC_SMEM_FLOATS * sizeof(float)>>>(x, Wk, bk, Wv, bv, pos);
    kD<<<BB * KK, 256, KD_SMEM_FLOATS * sizeof(float)>>>(cq, gam, bet, out);
}

// round 17
// speedup vs baseline: 2.7238x; 1.2492x over previous
#include <cuda_runtime.h>
#include <math.h>

#define BB   32
#define NN   16384
#define DD   65
#define CH   64
#define KK   64
#define NBL  256
#define NCHU 4
#define SCALE 0.1240347345892081f   /* 65^-0.5 */

// ---------------- scratch (device globals: no allocation allowed) ----------------
__device__ float g_partial[BB * 64 * DD];                 // per-(b,split) column sums
__device__ float g_q[BB * KK * DD];                       // queries (SCALE folded in)
__device__ float g_r[BB * DD];                            // gavg@Wr + br
__device__ float g_blk[(size_t)BB * KK * NBL * DD];       // block-attention output, 136 MB

__device__ __forceinline__ float gelu_exact(float v) {
    return 0.5f * v * (1.0f + erff(v * 0.70710678118654752f));
}

// ---- tf32 helpers ----
__device__ __forceinline__ unsigned cvt_tf32(float v) {
    unsigned r; asm("cvt.rna.tf32.f32 %0,%1;" : "=r"(r) : "f"(v)); return r;
}
__device__ __forceinline__ void mma_tf32(float* c,
    unsigned a0, unsigned a1, unsigned a2, unsigned a3,
    unsigned b0, unsigned b1) {
    asm("mma.sync.aligned.m16n8k8.row.col.f32.tf32.tf32.f32 "
        "{%0,%1,%2,%3},{%4,%5,%6,%7},{%8,%9},{%0,%1,%2,%3};"
        : "+f"(c[0]), "+f"(c[1]), "+f"(c[2]), "+f"(c[3])
        : "r"(a0), "r"(a1), "r"(a2), "r"(a3), "r"(b0), "r"(b1));
}

// ================= Kernel A: partial column sums of x over N =================
__global__ void kA(const float* __restrict__ x) {
    int b = blockIdx.y, s = blockIdx.x;
    int warp = threadIdx.x >> 5, lane = threadIdx.x & 31;
    const float* xb = x + ((size_t)b * NN + (size_t)s * 256 + warp * 32) * DD;
    float a0 = 0.f, a1 = 0.f, a2 = 0.f;
    #pragma unroll 4
    for (int r = 0; r < 32; ++r) {
        const float* row = xb + r * DD;
        a0 += row[lane];
        a1 += row[lane + 32];
        if (lane == 0) a2 += row[64];
    }
    __shared__ float sm[8][DD];
    sm[warp][lane] = a0;
    sm[warp][lane + 32] = a1;
    if (lane == 0) sm[warp][64] = a2;
    __syncthreads();
    if (threadIdx.x < DD) {
        float t = 0.f;
        #pragma unroll
        for (int w = 0; w < 8; ++w) t += sm[w][threadIdx.x];
        g_partial[(b * 64 + s) * DD + threadIdx.x] = t;
    }
}

// ================= Kernel B: gavg -> q (scaled), r = gavg@Wr+br =================
__global__ void kB(const float* __restrict__ Wq1, const float* __restrict__ bq1,
                   const float* __restrict__ Wq2, const float* __restrict__ bq2,
                   const float* __restrict__ Wr,  const float* __restrict__ br) {
    int b = blockIdx.x, slice = blockIdx.y;
    __shared__ float gavg[DD], h[DD];
    int t = threadIdx.x;
    if (t < DD) {
        float s = 0.f;
        for (int p = 0; p < 64; ++p) s += g_partial[(b * 64 + p) * DD + t];
        gavg[t] = s * (1.0f / (float)NN);
    }
    __syncthreads();
    if (t < DD) {
        float acc = bq1[t];
        for (int e = 0; e < DD; ++e) acc = fmaf(gavg[e], Wq1[e * DD + t], acc);
        h[t] = gelu_exact(acc);
        if (slice == 0) {
            float r = br[t];
            for (int e = 0; e < DD; ++e) r = fmaf(gavg[e], Wr[e * DD + t], r);
            g_r[b * DD + t] = r;
        }
    }
    __syncthreads();
    int jend = (slice + 1) * 260;
    for (int j = slice * 260 + t; j < jend; j += 256) {
        float acc = bq2[j];
        for (int e = 0; e < DD; ++e) acc = fmaf(h[e], Wq2[e * (KK * DD) + j], acc);
        g_q[b * KK * DD + j] = acc * SCALE;
    }
}

// ================= Kernel C: fused block attention, 4 chunks/CTA (tf32 mma) ==========
// grid (NBL/NCHU, B), 256 threads = 8 warps, 112064 B dynamic smem, 2 CTAs/SM.
// All GEMMs KS=8 (k=0..63); k=64 term added via exact fp32 scalar correction.
// Smem float layout:
//   X/PS [64][68]  x tf32 -> probs tf32 (aliased)    off 0      (4352)
//   WKV  [65][152] Wk cols 0..64 | Wv cols 72..136   off 4352   (9880)
//   QT   [64][68]  q tf32 (SCALE folded)             off 14232  (4352)
//   KB   [65][72]  keys^T tf32 [d][c]                off 18584  (4680)
//   VB   [64][72]  values tf32 [c][d]                off 23264  (4608)
//   SB   [144]     bias per WKV col                  off 27872  (144)
#define KC_SMEM_FLOATS 28016
#define OX   0
#define OWKV 4352
#define OQT  14232
#define OKB  18584
#define OVB  23264
#define OSB  27872

template<int NT>
__device__ __forceinline__ void mma_blk8(
    const unsigned* __restrict__ A, int la,
    const unsigned* __restrict__ B, int lb,
    int m0, int nbase, int nt,
    float (&acc)[NT][4], int g, int tg) {
    #pragma unroll
    for (int kt = 0; kt < 8; ++kt) {
        int k0 = kt * 8;
        unsigned a0 = A[(m0 + g) * la + k0 + tg];
        unsigned a1 = A[(m0 + g + 8) * la + k0 + tg];
        unsigned a2 = A[(m0 + g) * la + k0 + tg + 4];
        unsigned a3 = A[(m0 + g + 8) * la + k0 + tg + 4];
        #pragma unroll
        for (int i = 0; i < NT; ++i) {
            if (i < nt) {
                int n0 = (nbase + i) * 8;
                unsigned b0 = B[(k0 + tg) * lb + n0 + g];
                unsigned b1 = B[(k0 + tg + 4) * lb + n0 + g];
                mma_tf32(acc[i], a0, a1, a2, a3, b0, b1);
            }
        }
    }
}

__global__ __launch_bounds__(256, 2) void kC(
    const float* __restrict__ x,
    const float* __restrict__ Wk, const float* __restrict__ bk,
    const float* __restrict__ Wv, const float* __restrict__ bv,
    const float* __restrict__ pos) {
    extern __shared__ float sm[];
    unsigned* xsu  = (unsigned*)(sm + OX);
    float*    xsf  = sm + OX;
    float*    ps   = sm + OX;                 // probs alias X (X dead after KV GEMM)
    unsigned* psu  = (unsigned*)(sm + OX);
    unsigned* wkvu = (unsigned*)(sm + OWKV);
    float*    wkvf = sm + OWKV;
    unsigned* qtu  = (unsigned*)(sm + OQT);
    float*    qtf  = sm + OQT;
    unsigned* kBu  = (unsigned*)(sm + OKB);
    float*    kBf  = sm + OKB;
    unsigned* vBu  = (unsigned*)(sm + OVB);
    float*    sb   = sm + OSB;

    int t = threadIdx.x;
    int warp = t >> 5, lane = t & 31;
    int g = lane >> 2, tg = lane & 3;
    int wm = warp >> 1, wn = warp & 1;
    int m0 = wm * 16;
    int b = blockIdx.y;
    int ch0 = blockIdx.x * NCHU;

    // ---- one-time fills: WKV (tf32), QT (tf32), SB ----
    for (int i = t; i < 65 * 130; i += 256) {
        int e = i / 130, j = i - e * 130;
        int col = (j < 65) ? j : (j + 7);
        float v = (j < 65) ? Wk[e * DD + j] : Wv[e * DD + (j - 65)];
        wkvu[e * 152 + col] = cvt_tf32(v);
    }
    {
        const float* qb = g_q + (size_t)b * KK * DD;
        for (int i = t; i < KK * DD; i += 256) {
            int k = i / DD, d = i - k * DD;
            qtu[k * 68 + d] = cvt_tf32(qb[i]);
        }
    }
    if (t < DD) { sb[t] = bk[t]; sb[72 + t] = bv[t]; }

    // ---- prefetch chunk 0's x into registers ----
    float xr[17];
    {
        const float* xb0 = x + ((size_t)b * NN + (size_t)ch0 * CH) * DD;
        #pragma unroll
        for (int p = 0; p < 17; ++p) {
            int i = t + p * 256;
            xr[p] = (i < CH * DD) ? xb0[i] : 0.f;
        }
    }

    for (int ch = 0; ch < NCHU; ++ch) {
        int chunk = ch0 + ch;

        // ---- store prefetched x (tf32) into X ----
        #pragma unroll
        for (int p = 0; p < 17; ++p) {
            int i = t + p * 256;
            if (i < CH * DD) {
                int c = i / DD, e = i - c * DD;
                xsu[c * 68 + e] = cvt_tf32(xr[p]);
            }
        }
        __syncthreads();

        // ---- fused keys|values GEMM: [64x65] @ [65x(65|65)] ----
        {
            float acc[9][4] = {};
            int nbase = wn * 9;
            mma_blk8<9>(xsu, 68, wkvu, 152, m0, nbase, 9, acc, g, tg);
            int r0 = m0 + g, r1 = r0 + 8;
            float x64_0 = xsf[r0 * 68 + 64], x64_1 = xsf[r1 * 68 + 64];
            const float* pr0 = pos + r0 * DD;
            const float* pr1 = pos + r1 * DD;
            #pragma unroll
            for (int i = 0; i < 9; ++i) {
                int n0 = (nbase + i) * 8;
                #pragma unroll
                for (int e2 = 0; e2 < 2; ++e2) {
                    int col = n0 + 2 * tg + e2;
                    float w64 = wkvf[64 * 152 + col];
                    float a0v = fmaf(x64_0, w64, acc[i][e2]);
                    float a1v = fmaf(x64_1, w64, acc[i][2 + e2]);
                    float bi = sb[col];
                    if (col <= 64) {            // keys, d = col
                        int d = col;
                        float v0 = gelu_exact(a0v + bi) + pr0[d];
                        float v1 = gelu_exact(a1v + bi) + pr1[d];
                        kBu[d * 72 + r0] = cvt_tf32(v0);
                        kBu[d * 72 + r1] = cvt_tf32(v1);
                    } else if (col >= 72 && col <= 136) {   // values, d = col-72
                        int d = col - 72;
                        float v0 = gelu_exact(a0v + bi) + pr0[d];
                        float v1 = gelu_exact(a1v + bi) + pr1[d];
                        vBu[r0 * 72 + d] = cvt_tf32(v0);
                        vBu[r1 * 72 + d] = cvt_tf32(v1);
                    }
                }
            }
        }
        __syncthreads();

        // ---- prefetch next chunk's x (latency hidden behind scores/softmax/PV) ----
        if (ch + 1 < NCHU) {
            const float* xn = x + ((size_t)b * NN + (size_t)(chunk + 1) * CH) * DD;
            #pragma unroll
            for (int p = 0; p < 17; ++p) {
                int i = t + p * 256;
                xr[p] = (i < CH * DD) ? xn[i] : 0.f;
            }
        }

        // ---- scores[kq][c] = SCALE * (q @ keys^T) -> PS fp32 ----
        {
            float acc[4][4] = {};
            int nbase = wn * 4;
            mma_blk8<4>(qtu, 68, kBu, 72, m0, nbase, 4, acc, g, tg);
            int r0 = m0 + g, r1 = r0 + 8;
            float q64_0 = qtf[r0 * 68 + 64], q64_1 = qtf[r1 * 68 + 64];
            #pragma unroll
            for (int i = 0; i < 4; ++i) {
                int n0 = (nbase + i) * 8;
                #pragma unroll
                for (int e2 = 0; e2 < 2; ++e2) {
                    int c = n0 + 2 * tg + e2;
                    float k64 = kBf[64 * 72 + c];
                    ps[r0 * 68 + c] = fmaf(q64_0, k64, acc[i][e2]) * SCALE;
                    ps[r1 * 68 + c] = fmaf(q64_1, k64, acc[i][2 + e2]) * SCALE;
                }
            }
        }
        __syncthreads();

        // ---- softmax rows of PS (8 warps x 8 rows), store tf32 ----
        for (int row = warp; row < KK; row += 8) {
            float v0 = ps[row * 68 + lane], v1 = ps[row * 68 + lane + 32];
            float m = fmaxf(v0, v1);
            #pragma unroll
            for (int o = 16; o > 0; o >>= 1) m = fmaxf(m, __shfl_xor_sync(0xffffffffu, m, o));
            float e0 = __expf(v0 - m), e1 = __expf(v1 - m);
            float s = e0 + e1;
            #pragma unroll
            for (int o = 16; o > 0; o >>= 1) s += __shfl_xor_sync(0xffffffffu, s, o);
            float inv = 1.0f / s;
            psu[row * 68 + lane] = cvt_tf32(e0 * inv);
            psu[row * 68 + lane + 32] = cvt_tf32(e1 * inv);
        }
        __syncthreads();

        // ---- blk = P @ V -> g_blk[b][kq][chunk][d]  (K-dim = 64, exact) ----
        {
            float acc[5][4] = {};
            int nbase = wn * 5;
            int nt = wn ? 4 : 5;                 // tiles 0-4 | 5-8
            mma_blk8<5>(psu, 68, vBu, 72, m0, nbase, nt, acc, g, tg);
            int r0 = m0 + g, r1 = r0 + 8;
            size_t base0 = ((size_t)(b * KK + r0) * NBL + chunk) * DD;
            size_t base1 = ((size_t)(b * KK + r1) * NBL + chunk) * DD;
            #pragma unroll
            for (int i = 0; i < 5; ++i) if (i < nt) {
                int n0 = (nbase + i) * 8;
                #pragma unroll
                for (int e2 = 0; e2 < 2; ++e2) {
                    int d = n0 + 2 * tg + e2;
                    if (d < DD) {
                        g_blk[base0 + d] = acc[i][e2];
                        g_blk[base1 + d] = acc[i][2 + e2];
                    }
                }
            }
        }
        __syncthreads();
    }
}

// ================= Kernel D: cross-block attention + residual + LayerNorm =================
// grid (B*K), 256 threads, no staging: two direct gmem passes (2nd is L2/L1-resident),
// weighted sum parallel across 8 warps + smem cross-warp reduce. ~3.5 KB static smem.
__global__ __launch_bounds__(256, 6) void kD(
    const float* __restrict__ cq, const float* __restrict__ gamma,
    const float* __restrict__ beta, float* __restrict__ out) {
    __shared__ float scs[NBL];
    __shared__ float spart[8][68];
    __shared__ float swr[8];
    __shared__ float scomp[68];
    __shared__ float sfin[2];

    int t = threadIdx.x, warp = t >> 5, lane = t & 31;
    int bk = blockIdx.x;                 // = b*K + k
    int b = bk / KK;

    const float* src = g_blk + (size_t)bk * NBL * DD;
    float cq0 = cq[lane], cq1 = cq[lane + 32];
    float cq2 = (lane == 0) ? cq[64] : 0.f;

    // ---- pass 1: cs[n] = SCALE * cross_q . blk[n,:]  (blocked: warp w -> rows 32w..) ----
    {
        int n0 = warp * 32;
        #pragma unroll 4
        for (int i = 0; i < 32; ++i) {
            int n = n0 + i;
            const float* row = src + n * DD;
            float p = row[lane] * cq0 + row[lane + 32] * cq1;
            if (lane == 0) p += row[64] * cq2;
            #pragma unroll
            for (int o = 16; o > 0; o >>= 1) p += __shfl_xor_sync(0xffffffffu, p, o);
            if (lane == 0) scs[n] = p * SCALE;
        }
    }
    __syncthreads();

    // ---- softmax over 256 ----
    float v = scs[t];
    float m = v;
    #pragma unroll
    for (int o = 16; o > 0; o >>= 1) m = fmaxf(m, __shfl_xor_sync(0xffffffffu, m, o));
    if (lane == 0) swr[warp] = m;
    __syncthreads();
    if (t == 0) {
        float mm = swr[0];
        #pragma unroll
        for (int w = 1; w < 8; ++w) mm = fmaxf(mm, swr[w]);
        sfin[0] = mm;
    }
    __syncthreads();
    float e = __expf(v - sfin[0]);
    float s = e;
    #pragma unroll
    for (int o = 16; o > 0; o >>= 1) s += __shfl_xor_sync(0xffffffffu, s, o);
    if (lane == 0) swr[warp] = s;
    __syncthreads();
    if (t == 0) {
        float ts = 0.f;
        #pragma unroll
        for (int w = 0; w < 8; ++w) ts += swr[w];
        sfin[1] = ts;
    }
    __syncthreads();
    scs[t] = e / sfin[1];
    __syncthreads();

    // ---- pass 2: weighted sum, warp-parallel (same row blocks -> L1/L2 hits) ----
    {
        int n0 = warp * 32;
        float a0 = 0.f, a1 = 0.f, a2 = 0.f;
        #pragma unroll 4
        for (int i = 0; i < 32; ++i) {
            int n = n0 + i;
            float wn = scs[n];
            const float* row = src + n * DD;
            a0 = fmaf(wn, row[lane], a0);
            a1 = fmaf(wn, row[lane + 32], a1);
            if (lane == 0) a2 = fmaf(wn, row[64], a2);
        }
        spart[warp][lane] = a0;
        spart[warp][lane + 32] = a1;
        if (lane == 0) spart[warp][64] = a2;
    }
    __syncthreads();
    if (t < DD) {
        float a = 0.f;
        #pragma unroll
        for (int w = 0; w < 8; ++w) a += spart[w][t];
        scomp[t] = a + g_r[b * DD + t];
    }
    __syncthreads();

    if (t == 0) {
        float mu = 0.f;
        for (int d = 0; d < DD; ++d) mu += scomp[d];
        mu *= (1.0f / DD);
        float var = 0.f;
        for (int d = 0; d < DD; ++d) { float dv = scomp[d] - mu; var += dv * dv; }
        var *= (1.0f / DD);
        sfin[0] = mu;
        sfin[1] = rsqrtf(var + 1e-5f);
    }
    __syncthreads();
    if (t < DD)
        out[(size_t)bk * DD + t] = (scomp[t] - sfin[0]) * sfin[1] * gamma[t] + beta[t];
}

// ================= launch =================
extern "C" void kernel_launch(void* const* d_in, const int* in_sizes, int n_in,
                              void* d_out, int out_size) {
    (void)in_sizes; (void)n_in; (void)out_size;
    const float* x    = (const float*)d_in[0];
    const float* Wq1  = (const float*)d_in[1];
    const float* bq1  = (const float*)d_in[2];
    const float* Wq2  = (const float*)d_in[3];
    const float* bq2  = (const float*)d_in[4];
    const float* Wk   = (const float*)d_in[5];
    const float* bk   = (const float*)d_in[6];
    const float* Wv   = (const float*)d_in[7];
    const float* bv   = (const float*)d_in[8];
    const float* cq   = (const float*)d_in[9];
    const float* pos  = (const float*)d_in[10];
    const float* Wr   = (const float*)d_in[11];
    const float* br   = (const float*)d_in[12];
    const float* gam  = (const float*)d_in[13];
    const float* bet  = (const float*)d_in[14];
    float* out = (float*)d_out;

    cudaFuncSetAttribute(kC, cudaFuncAttributeMaxDynamicSharedMemorySize,
                         KC_SMEM_FLOATS * (int)sizeof(float));

    kA<<<dim3(64, BB), 256>>>(x);
    kB<<<dim3(BB, 16), 256>>>(Wq1, bq1, Wq2, bq2, Wr, br);
    kC<<<dim3(NBL / NCHU, BB), 256, KC_SMEM_FLOATS * sizeof(float)>>>(x, Wk, bk, Wv, bv, pos);
    kD<<<BB * KK, 256>>>(cq, gam, bet, out);
}